// round 2
// baseline (speedup 1.0000x reference)
#include <cuda_runtime.h>
#include <math.h>
#include <stdint.h>

#define NN 50000
#define EE 800000
#define CC 64

// ---------------- scratch (__device__ globals: allocation-free) ----------------
__device__ float    g_m[NN * CC];          // x @ W
__device__ float    g_cnt[NN];
__device__ float    g_s1[NN * CC];
__device__ float    g_s2[NN * CC];
__device__ unsigned g_mn[NN * CC];         // order-encoded float
__device__ unsigned g_mx[NN * CC];
__device__ float    g_agg[NN * 4 * CC];    // [mean | min | max | std]
__device__ float    g_a[NN];               // logd/avg_log
__device__ float    g_ia[NN];              // (logd/avg_log)*(avg_log/logd)  (~1, fp-rounded)
__device__ float    g_out_node[NN * CC];
__device__ float    g_gi[NN * 3 * CC];
__device__ float    g_gh[NN * 3 * CC];
__device__ float    g_avgsum[1];

// order-preserving float<->uint for atomic min/max
__device__ __forceinline__ unsigned f2o(float f) {
    unsigned u = __float_as_uint(f);
    return (u & 0x80000000u) ? ~u : (u | 0x80000000u);
}
__device__ __forceinline__ float o2f(unsigned u) {
    return (u & 0x80000000u) ? __uint_as_float(u ^ 0x80000000u) : __uint_as_float(~u);
}

// ---------------- init accumulators ----------------
__global__ void init_kernel(int N) {
    int idx = blockIdx.x * 256 + threadIdx.x;
    int total = N * CC;
    if (idx < total) {
        g_s1[idx] = 0.f;
        g_s2[idx] = 0.f;
        g_mn[idx] = 0xFFFFFFFFu;
        g_mx[idx] = 0u;
    }
    if (idx < N) g_cnt[idx] = 0.f;
    if (idx == 0) g_avgsum[0] = 0.f;
}

// ---------------- avg_log = mean(log(deg_hist+1)) ----------------
__global__ void avglog_kernel(const float* __restrict__ deg_hist, int N) {
    int idx = blockIdx.x * 256 + threadIdx.x;
    float v = (idx < N) ? logf(deg_hist[idx] + 1.f) : 0.f;
    #pragma unroll
    for (int o = 16; o; o >>= 1) v += __shfl_down_sync(0xFFFFFFFFu, v, o);
    __shared__ float sred[8];
    if ((threadIdx.x & 31) == 0) sred[threadIdx.x >> 5] = v;
    __syncthreads();
    if (threadIdx.x < 8) {
        v = sred[threadIdx.x];
        #pragma unroll
        for (int o = 4; o; o >>= 1) v += __shfl_down_sync(0xFFu, v, o);
        if (threadIdx.x == 0) atomicAdd(&g_avgsum[0], v);
    }
}

// ---------------- generic tiled SGEMM: C = A[MxK] @ B[KxNcol] (+bias) ----------------
// BM=BN=64, BK=16, 256 threads, 4x4 per-thread micro-tile. K % 16 == 0, Ncol % 64 == 0.
__global__ void gemm64(const float* __restrict__ A, const float* __restrict__ B,
                       const float* __restrict__ bias, float* __restrict__ Cout,
                       int M, int Ncol, int K) {
    __shared__ float As[16][64];
    __shared__ float Bs[16][64];
    int tid = threadIdx.x;
    int tr = tid / 16, tc = tid % 16;
    int mBase = blockIdx.y * 64;
    int nBase = blockIdx.x * 64;
    float acc[4][4] = {};
    int lr = tid / 4;           // A row 0..63
    int lk = (tid % 4) * 4;     // A k offset 0,4,8,12
    int br = tid / 16;          // B k row 0..15
    int bc = (tid % 16) * 4;    // B col offset

    for (int k0 = 0; k0 < K; k0 += 16) {
        int m = mBase + lr;
        float4 av = make_float4(0.f, 0.f, 0.f, 0.f);
        if (m < M) av = *reinterpret_cast<const float4*>(&A[(size_t)m * K + k0 + lk]);
        As[lk + 0][lr] = av.x; As[lk + 1][lr] = av.y;
        As[lk + 2][lr] = av.z; As[lk + 3][lr] = av.w;
        *reinterpret_cast<float4*>(&Bs[br][bc]) =
            *reinterpret_cast<const float4*>(&B[(size_t)(k0 + br) * Ncol + nBase + bc]);
        __syncthreads();
        #pragma unroll
        for (int k = 0; k < 16; k++) {
            float4 a4 = *reinterpret_cast<const float4*>(&As[k][tr * 4]);
            float4 b4 = *reinterpret_cast<const float4*>(&Bs[k][tc * 4]);
            float a[4] = {a4.x, a4.y, a4.z, a4.w};
            float b[4] = {b4.x, b4.y, b4.z, b4.w};
            #pragma unroll
            for (int i = 0; i < 4; i++)
                #pragma unroll
                for (int j = 0; j < 4; j++) acc[i][j] += a[i] * b[j];
        }
        __syncthreads();
    }
    float bs[4] = {0.f, 0.f, 0.f, 0.f};
    if (bias) {
        float4 t = *reinterpret_cast<const float4*>(&bias[nBase + tc * 4]);
        bs[0] = t.x; bs[1] = t.y; bs[2] = t.z; bs[3] = t.w;
    }
    #pragma unroll
    for (int i = 0; i < 4; i++) {
        int m = mBase + tr * 4 + i;
        if (m < M) {
            float4 o = make_float4(acc[i][0] + bs[0], acc[i][1] + bs[1],
                                   acc[i][2] + bs[2], acc[i][3] + bs[3]);
            *reinterpret_cast<float4*>(&Cout[(size_t)m * Ncol + nBase + tc * 4]) = o;
        }
    }
}

// ---------------- edge kernel: fused edge MLP + atomic segment reduce ----------------
// Block: 64 edges x 64 channels, K=192 in 3 phases of 64 (xi | xj | ea).
__global__ void edge_kernel(const float* __restrict__ edge_attr,
                            const int* __restrict__ edge_index,
                            const float* __restrict__ Wpre,
                            const float* __restrict__ We,
                            const float* __restrict__ be,
                            const float* __restrict__ bpre,
                            int E) {
    __shared__ float sIn[64][64];    // [k][edge]
    __shared__ float sW[64][64];     // [k][channel]
    __shared__ int   s_src[64], s_dst[64];
    __shared__ float s_ew[64];
    __shared__ float s_attr[64][3];
    __shared__ float sWe[3][64];
    __shared__ float sbe[64];
    __shared__ float sbpre[64];

    int tid = threadIdx.x;
    int eBase = blockIdx.x * 64;
    int ne = E - eBase; if (ne > 64) ne = 64;

    if (tid < 64) {
        bool v = tid < ne;
        int e = eBase + (v ? tid : 0);
        s_src[tid] = edge_index[e];
        s_dst[tid] = edge_index[E + e];
        float4 a4 = *reinterpret_cast<const float4*>(&edge_attr[(size_t)e * 4]);
        s_attr[tid][0] = a4.x; s_attr[tid][1] = a4.y; s_attr[tid][2] = a4.z;
        s_ew[tid] = v ? a4.w : 0.f;
        sbe[tid] = be[tid];
        sbpre[tid] = bpre[tid];
    } else if (tid < 64 + 192) {
        int t = tid - 64;
        sWe[t / 64][t % 64] = We[t];
    }
    __syncthreads();
    if (tid < ne) atomicAdd(&g_cnt[s_dst[tid]], 1.0f);

    int tr = tid / 16, tc = tid % 16;
    float acc[4][4] = {};
    int le = tid & 63;
    int lk4 = tid >> 6;   // 0..3

    #pragma unroll 1
    for (int ph = 0; ph < 3; ph++) {
        // stage Wpre rows [ph*64, ph*64+64)
        {
            int r = tid / 4;
            int cq = (tid % 4) * 4;
            #pragma unroll
            for (int q = 0; q < 4; q++) {
                int c = cq + q * 16;
                *reinterpret_cast<float4*>(&sW[r][c]) =
                    *reinterpret_cast<const float4*>(&Wpre[(size_t)(ph * 64 + r) * 64 + c]);
            }
        }
        // build input tile
        {
            float ew = s_ew[le];
            if (ph < 2) {
                int node = (ph == 0) ? s_dst[le] : s_src[le];
                const float* mp = &g_m[(size_t)node * 64];
                #pragma unroll
                for (int kk = 0; kk < 4; kk++) {
                    int k = lk4 * 16 + kk * 4;
                    float4 v = *reinterpret_cast<const float4*>(&mp[k]);
                    sIn[k + 0][le] = ew * v.x; sIn[k + 1][le] = ew * v.y;
                    sIn[k + 2][le] = ew * v.z; sIn[k + 3][le] = ew * v.w;
                }
            } else {
                float a0 = s_attr[le][0], a1 = s_attr[le][1], a2 = s_attr[le][2];
                #pragma unroll
                for (int kk = 0; kk < 4; kk++) {
                    int k = lk4 * 16 + kk * 4;
                    float4 w0 = *reinterpret_cast<const float4*>(&sWe[0][k]);
                    float4 w1 = *reinterpret_cast<const float4*>(&sWe[1][k]);
                    float4 w2 = *reinterpret_cast<const float4*>(&sWe[2][k]);
                    float4 bb = *reinterpret_cast<const float4*>(&sbe[k]);
                    sIn[k + 0][le] = ew * (a0 * w0.x + a1 * w1.x + a2 * w2.x + bb.x);
                    sIn[k + 1][le] = ew * (a0 * w0.y + a1 * w1.y + a2 * w2.y + bb.y);
                    sIn[k + 2][le] = ew * (a0 * w0.z + a1 * w1.z + a2 * w2.z + bb.z);
                    sIn[k + 3][le] = ew * (a0 * w0.w + a1 * w1.w + a2 * w2.w + bb.w);
                }
            }
        }
        __syncthreads();
        #pragma unroll 16
        for (int k = 0; k < 64; k++) {
            float4 a4 = *reinterpret_cast<const float4*>(&sIn[k][tr * 4]);
            float4 b4 = *reinterpret_cast<const float4*>(&sW[k][tc * 4]);
            float a[4] = {a4.x, a4.y, a4.z, a4.w};
            float b[4] = {b4.x, b4.y, b4.z, b4.w};
            #pragma unroll
            for (int i = 0; i < 4; i++)
                #pragma unroll
                for (int j = 0; j < 4; j++) acc[i][j] += a[i] * b[j];
        }
        __syncthreads();
    }

    // epilogue: atomic segment reductions keyed by dst
    #pragma unroll
    for (int i = 0; i < 4; i++) {
        int e = tr * 4 + i;
        if (e < ne) {
            int d = s_dst[e];
            size_t base = (size_t)d * 64 + tc * 4;
            #pragma unroll
            for (int j = 0; j < 4; j++) {
                float h = acc[i][j] + sbpre[tc * 4 + j];
                atomicAdd(&g_s1[base + j], h);
                atomicAdd(&g_s2[base + j], h * h);
                unsigned o = f2o(h);
                atomicMin(&g_mn[base + j], o);
                atomicMax(&g_mx[base + j], o);
            }
        }
    }
}

// ---------------- per-node aggregate finalize ----------------
__global__ void node_kernel(int N) {
    int idx = blockIdx.x * 256 + threadIdx.x;
    if (idx >= N * CC) return;
    int n = idx >> 6, c = idx & 63;
    float cnt = g_cnt[n];
    float safe = fmaxf(cnt, 1.f);
    float inv = 1.f / safe;
    float mean = g_s1[idx] * inv;
    float msq  = g_s2[idx] * inv;
    float var  = msq - mean * mean;
    float stdv = sqrtf(fmaxf(var, 0.f) + 1e-5f);
    float mnf = 0.f, mxf = 0.f;
    if (cnt > 0.f) { mnf = o2f(g_mn[idx]); mxf = o2f(g_mx[idx]); }
    size_t b = (size_t)n * 256;
    g_agg[b + c]       = mean;
    g_agg[b + 64 + c]  = mnf;
    g_agg[b + 128 + c] = mxf;
    g_agg[b + 192 + c] = stdv;
    if (c == 0) {
        float avg = g_avgsum[0] / (float)N;
        float logd = logf(safe + 1.f);
        float a = logd / avg;          // o2 scale
        g_a[n]  = a;
        // o3 = o2 * (avg/logd) = o1 * (a * (avg/logd)); the factors cancel in
        // exact math — compute the composed scale to match reference semantics.
        g_ia[n] = a * (avg / logd);
    }
}

// ---------------- Wpost GEMM with on-the-fly z construction ----------------
// z[n] = [m(64) | agg(256) | a*agg(256) | (a*ia)*agg(256)], K=832, out 64 wide.
__global__ void gemm_post(const float* __restrict__ Wpost, const float* __restrict__ bpost,
                          int M) {
    __shared__ float As[16][64];
    __shared__ float Bs[16][64];
    int tid = threadIdx.x;
    int tr = tid / 16, tc = tid % 16;
    int mBase = blockIdx.y * 64;
    float acc[4][4] = {};
    int lr = tid / 4;
    int lk = (tid % 4) * 4;
    int br = tid / 16;
    int bc = (tid % 16) * 4;

    for (int k0 = 0; k0 < 832; k0 += 16) {
        int m = mBase + lr;
        float4 av = make_float4(0.f, 0.f, 0.f, 0.f);
        if (m < M) {
            int k = k0 + lk;
            float sc = 1.f;
            const float* src;
            if (k < 64)       src = &g_m[(size_t)m * 64 + k];
            else if (k < 320) src = &g_agg[(size_t)m * 256 + (k - 64)];
            else if (k < 576) { src = &g_agg[(size_t)m * 256 + (k - 320)]; sc = g_a[m]; }
            else              { src = &g_agg[(size_t)m * 256 + (k - 576)]; sc = g_ia[m]; }
            av = *reinterpret_cast<const float4*>(src);
            av.x *= sc; av.y *= sc; av.z *= sc; av.w *= sc;
        }
        As[lk + 0][lr] = av.x; As[lk + 1][lr] = av.y;
        As[lk + 2][lr] = av.z; As[lk + 3][lr] = av.w;
        *reinterpret_cast<float4*>(&Bs[br][bc]) =
            *reinterpret_cast<const float4*>(&Wpost[(size_t)(k0 + br) * 64 + bc]);
        __syncthreads();
        #pragma unroll
        for (int k = 0; k < 16; k++) {
            float4 a4 = *reinterpret_cast<const float4*>(&As[k][tr * 4]);
            float4 b4 = *reinterpret_cast<const float4*>(&Bs[k][tc * 4]);
            float a[4] = {a4.x, a4.y, a4.z, a4.w};
            float b[4] = {b4.x, b4.y, b4.z, b4.w};
            #pragma unroll
            for (int i = 0; i < 4; i++)
                #pragma unroll
                for (int j = 0; j < 4; j++) acc[i][j] += a[i] * b[j];
        }
        __syncthreads();
    }
    float4 bt = *reinterpret_cast<const float4*>(&bpost[tc * 4]);
    float bs[4] = {bt.x, bt.y, bt.z, bt.w};
    #pragma unroll
    for (int i = 0; i < 4; i++) {
        int m = mBase + tr * 4 + i;
        if (m < M) {
            float4 o = make_float4(acc[i][0] + bs[0], acc[i][1] + bs[1],
                                   acc[i][2] + bs[2], acc[i][3] + bs[3]);
            *reinterpret_cast<float4*>(&g_out_node[(size_t)m * 64 + tc * 4]) = o;
        }
    }
}

// ---------------- GRU elementwise ----------------
__global__ void gru_kernel(const float* __restrict__ x, float* __restrict__ out, int N) {
    int idx = blockIdx.x * 256 + threadIdx.x;
    if (idx >= N * CC) return;
    int n = idx >> 6, c = idx & 63;
    size_t b = (size_t)n * 192;
    float ir = g_gi[b + c],       hr = g_gh[b + c];
    float iz = g_gi[b + 64 + c],  hz = g_gh[b + 64 + c];
    float in_ = g_gi[b + 128 + c], hn = g_gh[b + 128 + c];
    float r = 1.f / (1.f + expf(-(ir + hr)));
    float z = 1.f / (1.f + expf(-(iz + hz)));
    float nn = tanhf(in_ + r * hn);
    out[idx] = (1.f - z) * nn + z * x[idx];
}

// ---------------- launch ----------------
extern "C" void kernel_launch(void* const* d_in, const int* in_sizes, int n_in,
                              void* d_out, int out_size) {
    const float* x         = (const float*)d_in[0];
    const float* edge_attr = (const float*)d_in[1];
    const float* deg_hist  = (const float*)d_in[2];
    const float* W         = (const float*)d_in[3];
    const float* We        = (const float*)d_in[4];
    const float* be        = (const float*)d_in[5];
    const float* Wpre      = (const float*)d_in[6];
    const float* bpre      = (const float*)d_in[7];
    const float* Wpost     = (const float*)d_in[8];
    const float* bpost     = (const float*)d_in[9];
    const float* Wih       = (const float*)d_in[10];
    const float* bih       = (const float*)d_in[11];
    const float* Whh       = (const float*)d_in[12];
    const float* bhh       = (const float*)d_in[13];
    const int*   edge_index = (const int*)d_in[14];

    int N = in_sizes[0] / CC;
    int E = in_sizes[14] / 2;

    float *pm, *pon, *pgi, *pgh;
    cudaGetSymbolAddress((void**)&pm,  g_m);
    cudaGetSymbolAddress((void**)&pon, g_out_node);
    cudaGetSymbolAddress((void**)&pgi, g_gi);
    cudaGetSymbolAddress((void**)&pgh, g_gh);

    int nodeElems = N * CC;
    init_kernel<<<(nodeElems + 255) / 256, 256>>>(N);
    avglog_kernel<<<(N + 255) / 256, 256>>>(deg_hist, N);
    gemm64<<<dim3(1, (N + 63) / 64), 256>>>(x, W, nullptr, pm, N, 64, 64);
    edge_kernel<<<(E + 63) / 64, 256>>>(edge_attr, edge_index, Wpre, We, be, bpre, E);
    node_kernel<<<(nodeElems + 255) / 256, 256>>>(N);
    gemm_post<<<dim3(1, (N + 63) / 64), 256>>>(Wpost, bpost, N);
    gemm64<<<dim3(3, (N + 63) / 64), 256>>>(pon, Wih, bih, pgi, N, 192, 64);
    gemm64<<<dim3(3, (N + 63) / 64), 256>>>(x, Whh, bhh, pgh, N, 192, 64);
    gru_kernel<<<(nodeElems + 255) / 256, 256>>>(x, (float*)d_out, N);
}